// round 1
// baseline (speedup 1.0000x reference)
#include <cuda_runtime.h>
#include <math.h>

#define kVocab 50000
#define kEmbed 300
#define kUnits 512
#define kT 128
#define kB 512
#define kG 2048  /* 4*UNITS */

// Scratch: pre-activation input projection Zpre[b*T+t][2048] and running c state.
__device__ float g_zpre[(size_t)kB * kT * kG];   // 512 MB
__device__ float g_c[(size_t)kB * kUnits];

// ---------------------------------------------------------------------------
// Precompute: Zpre[m][n] = bias[n] + sum_e emb[seq[m]][e] * W[e][n]
// m = b*T + t (matches input_sequence row-major layout).
// Tile: 128(M) x 128(N) x 32(K), 256 threads, 8x8 micro-tile.
// ---------------------------------------------------------------------------
__global__ __launch_bounds__(256) void precompute_kernel(
    const int* __restrict__ seq, const float* __restrict__ emb,
    const float* __restrict__ W, const float* __restrict__ bias)
{
    __shared__ float As[32][128];   // [k][m]
    __shared__ float Bs[32][128];   // [k][n]
    __shared__ int toks[128];

    const int tid = threadIdx.x;
    const int tx = tid & 15, ty = tid >> 4;
    const int m0 = blockIdx.y * 128;
    const int n0 = blockIdx.x * 128;

    if (tid < 128) toks[tid] = seq[m0 + tid];
    __syncthreads();

    float acc[8][8];
#pragma unroll
    for (int i = 0; i < 8; i++)
#pragma unroll
        for (int j = 0; j < 8; j++) acc[i][j] = 0.f;

    const int ar = tid >> 1;            // A gather row 0..127
    const int aseg = (tid & 1) * 16;    // A k-segment 0 or 16
    const int bk = tid >> 3;            // B k-row 0..31
    const int bc = (tid & 7) * 16;      // B col segment
    const float* erow = emb + (size_t)toks[ar] * kEmbed;

    for (int k0 = 0; k0 < 320; k0 += 32) {   // K=300 padded to 320
        // A tile: gathered embedding rows, transposed into [k][m]
#pragma unroll
        for (int i = 0; i < 16; i++) {
            int k = k0 + aseg + i;
            As[aseg + i][ar] = (k < kEmbed) ? __ldg(erow + k) : 0.f;
        }
        // B tile: W rows (predicated on k < 300)
        {
            int k = k0 + bk;
            bool v = (k < kEmbed);
            const float4* wrow = (const float4*)(W + (size_t)k * kG + n0 + bc);
#pragma unroll
            for (int i = 0; i < 4; i++) {
                float4 val = v ? __ldg(wrow + i) : make_float4(0.f, 0.f, 0.f, 0.f);
                *(float4*)&Bs[bk][bc + i * 4] = val;
            }
        }
        __syncthreads();
#pragma unroll
        for (int k = 0; k < 32; k++) {
            float a[8], b[8];
            *(float4*)(a)     = *(const float4*)&As[k][ty * 8];
            *(float4*)(a + 4) = *(const float4*)&As[k][ty * 8 + 4];
            *(float4*)(b)     = *(const float4*)&Bs[k][tx * 8];
            *(float4*)(b + 4) = *(const float4*)&Bs[k][tx * 8 + 4];
#pragma unroll
            for (int i = 0; i < 8; i++)
#pragma unroll
                for (int j = 0; j < 8; j++)
                    acc[i][j] = fmaf(a[i], b[j], acc[i][j]);
        }
        __syncthreads();
    }

    float bv[8];
#pragma unroll
    for (int j = 0; j < 8; j++) bv[j] = bias[n0 + tx * 8 + j];
#pragma unroll
    for (int i = 0; i < 8; i++) {
        size_t m = (size_t)(m0 + ty * 8 + i);
        float* orow = g_zpre + m * kG + (n0 + tx * 8);
        float4 o0 = make_float4(acc[i][0] + bv[0], acc[i][1] + bv[1],
                                acc[i][2] + bv[2], acc[i][3] + bv[3]);
        float4 o1 = make_float4(acc[i][4] + bv[4], acc[i][5] + bv[5],
                                acc[i][6] + bv[6], acc[i][7] + bv[7]);
        *(float4*)orow       = o0;
        *(float4*)(orow + 4) = o1;
    }
}

// ---------------------------------------------------------------------------
// One LSTM step: z = Zpre[:,t,:] + h_{t-1} @ U ; gates; mask; write h_t into
// enc_output slice t of d_out; carry c in g_c.
// Tile: 32 batch rows x 64 units (x 4 gates -> N=256 GEMM cols), 256 threads.
// Each thread: 2 rows x (4 units x 4 gates) = fused cell for 2x4 (b,u) cells.
// ---------------------------------------------------------------------------
__global__ __launch_bounds__(256) void step_kernel(
    const float* __restrict__ hprev, int hstride,
    const float* __restrict__ c0,
    const int* __restrict__ seq,
    const float* __restrict__ Umat,
    float* __restrict__ out, int t)
{
    __shared__ float As[32][32];    // [k][b]
    __shared__ float Bs[32][256];   // [k][j], j = gate*64 + u_local

    const int tid = threadIdx.x;
    const int tx = tid & 15, ty = tid >> 4;
    const int b0 = blockIdx.y * 32;
    const int u0 = blockIdx.x * 64;

    const float* cin = (t == 0) ? c0 : g_c;

    float acc[2][16];
#pragma unroll
    for (int r = 0; r < 2; r++)
#pragma unroll
        for (int j = 0; j < 16; j++) acc[r][j] = 0.f;

    const int ar = tid >> 3;           // h row 0..31
    const int ak = (tid & 7) * 4;      // h k-offset
    const int bkk = tid >> 3;          // U k-row 0..31
    const int bj = (tid & 7) * 32;     // U j-segment

    for (int k0 = 0; k0 < kUnits; k0 += 32) {
        // A tile: h rows (strided when reading from enc_output), transpose to [k][b]
        float4 av = *(const float4*)(hprev + (size_t)(b0 + ar) * hstride + k0 + ak);
        As[ak + 0][ar] = av.x;
        As[ak + 1][ar] = av.y;
        As[ak + 2][ar] = av.z;
        As[ak + 3][ar] = av.w;
        // B tile: U columns for 4 gate groups
        const float* ubase = Umat + (size_t)(k0 + bkk) * kG;
#pragma unroll
        for (int i = 0; i < 8; i++) {
            int j = bj + i * 4;
            int n = ((j >> 6) << 9) + u0 + (j & 63);
            *(float4*)&Bs[bkk][j] = __ldg((const float4*)(ubase + n));
        }
        __syncthreads();
#pragma unroll
        for (int k = 0; k < 32; k++) {
            float2 a = *(const float2*)&As[k][ty * 2];
#pragma unroll
            for (int g = 0; g < 4; g++) {
                float4 bv = *(const float4*)&Bs[k][g * 64 + tx * 4];
                acc[0][g * 4 + 0] = fmaf(a.x, bv.x, acc[0][g * 4 + 0]);
                acc[0][g * 4 + 1] = fmaf(a.x, bv.y, acc[0][g * 4 + 1]);
                acc[0][g * 4 + 2] = fmaf(a.x, bv.z, acc[0][g * 4 + 2]);
                acc[0][g * 4 + 3] = fmaf(a.x, bv.w, acc[0][g * 4 + 3]);
                acc[1][g * 4 + 0] = fmaf(a.y, bv.x, acc[1][g * 4 + 0]);
                acc[1][g * 4 + 1] = fmaf(a.y, bv.y, acc[1][g * 4 + 1]);
                acc[1][g * 4 + 2] = fmaf(a.y, bv.z, acc[1][g * 4 + 2]);
                acc[1][g * 4 + 3] = fmaf(a.y, bv.w, acc[1][g * 4 + 3]);
            }
        }
        __syncthreads();
    }

    // Fused LSTM cell epilogue
#pragma unroll
    for (int rr = 0; rr < 2; rr++) {
        int b = b0 + ty * 2 + rr;
        size_t bt = (size_t)b * kT + t;
        bool msk = (seq[bt] != 0);
        const float* zp = g_zpre + bt * (size_t)kG;
#pragma unroll
        for (int c = 0; c < 4; c++) {
            int u = u0 + tx * 4 + c;
            float zi = acc[rr][0  + c] + zp[u];
            float zf = acc[rr][4  + c] + zp[512 + u];
            float zg = acc[rr][8  + c] + zp[1024 + u];
            float zo = acc[rr][12 + c] + zp[1536 + u];
            float ig = 1.f / (1.f + expf(-zi));
            float fg = 1.f / (1.f + expf(-zf));
            float og = 1.f / (1.f + expf(-zo));
            float cold = cin[(size_t)b * kUnits + u];
            float cnew = fg * cold + ig * tanhf(zg);
            float hnew = og * tanhf(cnew);
            if (!msk) {
                cnew = cold;
                hnew = hprev[(size_t)b * hstride + u];
            }
            out[(size_t)b * (kT * kUnits) + (size_t)t * kUnits + u] = hnew;
            g_c[(size_t)b * kUnits + u] = cnew;
        }
    }
}

// ---------------------------------------------------------------------------
// Finalize: h_fin = enc_output[:, T-1, :], c_fin = g_c
// ---------------------------------------------------------------------------
__global__ __launch_bounds__(256) void finalize_kernel(float* __restrict__ out)
{
    int i = blockIdx.x * blockDim.x + threadIdx.x;
    if (i < kB * kUnits) {
        int b = i / kUnits;
        int u = i - b * kUnits;
        float* hfin = out + (size_t)kB * kT * kUnits;
        float* cfin = hfin + (size_t)kB * kUnits;
        hfin[i] = out[(size_t)b * (kT * kUnits) + (size_t)(kT - 1) * kUnits + u];
        cfin[i] = g_c[i];
    }
}

// ---------------------------------------------------------------------------
extern "C" void kernel_launch(void* const* d_in, const int* in_sizes, int n_in,
                              void* d_out, int out_size)
{
    const int*   seq  = (const int*)d_in[0];
    const float* h0   = (const float*)d_in[1];
    const float* c0   = (const float*)d_in[2];
    const float* emb  = (const float*)d_in[3];
    const float* W    = (const float*)d_in[4];
    const float* Umat = (const float*)d_in[5];
    const float* bias = (const float*)d_in[6];
    float* out = (float*)d_out;

    // 1) Input projection for all (b, t) in parallel
    precompute_kernel<<<dim3(kG / 128, (kB * kT) / 128), 256>>>(seq, emb, W, bias);

    // 2) Sequential recurrence; h_{t-1} read from enc_output slice t-1
    for (int t = 0; t < kT; t++) {
        const float* hprev = t ? (out + (size_t)(t - 1) * kUnits) : h0;
        int hstride = t ? (kT * kUnits) : kUnits;
        step_kernel<<<dim3(kUnits / 64, kB / 32), 256>>>(
            hprev, hstride, c0, seq, Umat, out, t);
    }

    // 3) Copy final states to output tail
    finalize_kernel<<<(kB * kUnits + 255) / 256, 256>>>(out);
}

// round 3
// speedup vs baseline: 3.1074x; 3.1074x over previous
#include <cuda_runtime.h>
#include <cuda_bf16.h>
#include <cstdint>
#include <math.h>

#define kEmbed 300
#define kUnits 512
#define kT 128
#define kB 512
#define kG 2048  /* 4*UNITS */

// ---------------- global scratch ----------------
__device__ float g_zpre[(size_t)kB * kT * kG];                 // pre-activations [b*T+t][2048]
__device__ float g_c[(size_t)kB * kUnits];                     // c state [b][u]
__device__ __align__(128) __nv_bfloat16 g_u_hi[kG * kUnits];   // U^T gate-interleaved [n'][k]
__device__ __align__(128) __nv_bfloat16 g_u_lo[kG * kUnits];
__device__ __align__(128) __nv_bfloat16 g_hb_hi[2][kB * kUnits]; // h bf16 hi, double buffered [b][k]
__device__ __align__(128) __nv_bfloat16 g_hb_lo[2][kB * kUnits];

// ---------------- helpers ----------------
__device__ __forceinline__ uint32_t smem_u32(const void* p) {
    uint32_t a;
    asm("{ .reg .u64 t; cvta.to.shared.u64 t, %1; cvt.u32.u64 %0, t; }" : "=r"(a) : "l"(p));
    return a;
}
#define CP_ASYNC16(dst, src) \
    asm volatile("cp.async.ca.shared.global [%0], [%1], 16;" :: "r"(dst), "l"(src) : "memory")
#define CP_COMMIT() asm volatile("cp.async.commit_group;" ::: "memory")
#define CP_WAIT0()  asm volatile("cp.async.wait_group 0;" ::: "memory")

#define LDMATRIX_X4(r0, r1, r2, r3, addr) \
    asm volatile("ldmatrix.sync.aligned.m8n8.x4.shared.b16 {%0,%1,%2,%3}, [%4];" \
        : "=r"(r0), "=r"(r1), "=r"(r2), "=r"(r3) : "r"(addr))

#define MMA_BF16(c0, c1, c2, c3, a0, a1, a2, a3, b0, b1) \
    asm volatile("mma.sync.aligned.m16n8k16.row.col.f32.bf16.bf16.f32 " \
        "{%0,%1,%2,%3}, {%4,%5,%6,%7}, {%8,%9}, {%0,%1,%2,%3};" \
        : "+f"(c0), "+f"(c1), "+f"(c2), "+f"(c3) \
        : "r"(a0), "r"(a1), "r"(a2), "r"(a3), "r"(b0), "r"(b1))

__device__ __forceinline__ float fast_ex2(float x) { float y; asm("ex2.approx.ftz.f32 %0, %1;" : "=f"(y) : "f"(x)); return y; }
__device__ __forceinline__ float fast_sig(float x) { return __fdividef(1.f, 1.f + fast_ex2(-1.4426950408889634f * x)); }
__device__ __forceinline__ float fast_tanh(float x) {
    float ax = fabsf(x);
    float e = fast_ex2(-2.8853900817779268f * ax);
    float t = __fdividef(1.f - e, 1.f + e);
    return copysignf(t, x);
}

// ---------------- prep: split/transpose U, split h0 ----------------
__global__ __launch_bounds__(128) void prep_kernel(const float* __restrict__ U,
                                                   const float* __restrict__ h0) {
    int blk = blockIdx.x;
    if (blk < kG) {                       // Uprep row n' = u*4 + g  <-  U[:, g*512+u]
        int np = blk;
        int n = (np & 3) * kUnits + (np >> 2);
        for (int k = threadIdx.x; k < kUnits; k += 128) {
            float v = __ldg(U + (size_t)k * kG + n);
            __nv_bfloat16 hi = __float2bfloat16(v);
            g_u_hi[np * kUnits + k] = hi;
            g_u_lo[np * kUnits + k] = __float2bfloat16(v - __bfloat162float(hi));
        }
    } else {                              // h0 -> bf16 hi/lo into buffer 1
        int r0 = (blk - kG) * 64;
        for (int i = threadIdx.x; i < 64 * kUnits; i += 128) {
            int r = r0 + (i >> 9), k = i & 511;
            float v = __ldg(h0 + (size_t)r * kUnits + k);
            __nv_bfloat16 hi = __float2bfloat16(v);
            g_hb_hi[1][r * kUnits + k] = hi;
            g_hb_lo[1][r * kUnits + k] = __float2bfloat16(v - __bfloat162float(hi));
        }
    }
}

// ---------------- precompute Zpre (SIMT fp32) ----------------
__global__ __launch_bounds__(256) void precompute_kernel(
    const int* __restrict__ seq, const float* __restrict__ emb,
    const float* __restrict__ W, const float* __restrict__ bias)
{
    __shared__ float As[32][128];
    __shared__ float Bs[32][128];
    __shared__ int toks[128];

    const int tid = threadIdx.x;
    const int tx = tid & 15, ty = tid >> 4;
    const int m0 = blockIdx.y * 128;
    const int n0 = blockIdx.x * 128;

    if (tid < 128) toks[tid] = seq[m0 + tid];
    __syncthreads();

    float acc[8][8];
#pragma unroll
    for (int i = 0; i < 8; i++)
#pragma unroll
        for (int j = 0; j < 8; j++) acc[i][j] = 0.f;

    const int ar = tid >> 1;
    const int aseg = (tid & 1) * 16;
    const int bk = tid >> 3;
    const int bc = (tid & 7) * 16;
    const float* erow = emb + (size_t)toks[ar] * kEmbed;

    for (int k0 = 0; k0 < 320; k0 += 32) {
#pragma unroll
        for (int i = 0; i < 16; i++) {
            int k = k0 + aseg + i;
            As[aseg + i][ar] = (k < kEmbed) ? __ldg(erow + k) : 0.f;
        }
        {
            int k = k0 + bk;
            bool v = (k < kEmbed);
            const float4* wrow = (const float4*)(W + (size_t)k * kG + n0 + bc);
#pragma unroll
            for (int i = 0; i < 4; i++) {
                float4 val = v ? __ldg(wrow + i) : make_float4(0.f, 0.f, 0.f, 0.f);
                *(float4*)&Bs[bk][bc + i * 4] = val;
            }
        }
        __syncthreads();
#pragma unroll
        for (int k = 0; k < 32; k++) {
            float a[8], b[8];
            *(float4*)(a)     = *(const float4*)&As[k][ty * 8];
            *(float4*)(a + 4) = *(const float4*)&As[k][ty * 8 + 4];
            *(float4*)(b)     = *(const float4*)&Bs[k][tx * 8];
            *(float4*)(b + 4) = *(const float4*)&Bs[k][tx * 8 + 4];
#pragma unroll
            for (int i = 0; i < 8; i++)
#pragma unroll
                for (int j = 0; j < 8; j++)
                    acc[i][j] = fmaf(a[i], b[j], acc[i][j]);
        }
        __syncthreads();
    }

    float bv[8];
#pragma unroll
    for (int j = 0; j < 8; j++) bv[j] = bias[n0 + tx * 8 + j];
#pragma unroll
    for (int i = 0; i < 8; i++) {
        size_t m = (size_t)(m0 + ty * 8 + i);
        float* orow = g_zpre + m * kG + (n0 + tx * 8);
        *(float4*)orow       = make_float4(acc[i][0] + bv[0], acc[i][1] + bv[1],
                                           acc[i][2] + bv[2], acc[i][3] + bv[3]);
        *(float4*)(orow + 4) = make_float4(acc[i][4] + bv[4], acc[i][5] + bv[5],
                                           acc[i][6] + bv[6], acc[i][7] + bv[7]);
    }
}

// ---------------- mma.sync LSTM step ----------------
// grid (32 n-tiles, 8 m-tiles), 128 threads (4 warps).
// CTA tile: M=64 batch x N=64 n' (16 units x 4 gates), K=512 in 8 chunks of 64.
// Warp tile 32x32. bf16 3-pass: hi*hi + hi*lo + lo*hi, fp32 register accum.
// SMEM: 2 buffers x 4 matrices (A_hi, A_lo, B_hi, B_lo) x 8KB = 64KB.
#define SMEM_TILE(buf, mat) ((buf) * 32768 + (mat) * 8192)
#define DYN_SMEM 65536

extern "C" __global__ void __launch_bounds__(128) step_mma_kernel(
    int t,
    const int* __restrict__ seq,
    const float* __restrict__ hprev_f32, int hstride,
    const float* __restrict__ c0,
    float* __restrict__ out)
{
    extern __shared__ __align__(1024) char smp[];
    const uint32_t smb = smem_u32(smp);

    const int tid = threadIdx.x;
    const int wid = tid >> 5, lane = tid & 31;
    const int nt = blockIdx.x, mt = blockIdx.y;
    const int b0 = mt * 64;
    const int n0 = nt * 64;
    const int u0g = nt * 16;

    const __nv_bfloat16* srcA_hi = g_hb_hi[(t + 1) & 1] + (size_t)b0 * kUnits;
    const __nv_bfloat16* srcA_lo = g_hb_lo[(t + 1) & 1] + (size_t)b0 * kUnits;
    const __nv_bfloat16* srcB_hi = g_u_hi + (size_t)n0 * kUnits;
    const __nv_bfloat16* srcB_lo = g_u_lo + (size_t)n0 * kUnits;

    // warp sub-tile origin
    const int wm = (wid & 1) * 32;   // rows in A tile
    const int wn = (wid >> 1) * 32;  // rows in B tile (n')

    float acc[2][4][4];
#pragma unroll
    for (int i = 0; i < 2; i++)
#pragma unroll
        for (int j = 0; j < 4; j++)
#pragma unroll
            for (int q = 0; q < 4; q++) acc[i][j][q] = 0.f;

    // ---- async load of one K-chunk (64 wide) into buffer buf ----
    auto issue_chunk = [&](int kc, int buf) {
#pragma unroll
        for (int i = 0; i < 16; i++) {
            int idx = i * 128 + tid;            // 0..2047
            int mat = i >> 2;                   // constant per i
            int r = (idx >> 3) & 63, q = idx & 7;
            const __nv_bfloat16* s =
                (mat == 0) ? srcA_hi : (mat == 1) ? srcA_lo : (mat == 2) ? srcB_hi : srcB_lo;
            const __nv_bfloat16* sp = s + (size_t)r * kUnits + kc * 64 + q * 8;
            uint32_t off = (uint32_t)(r * 128 + q * 16);
            off ^= (uint32_t)((r & 7) * 16);    // XOR swizzle
            CP_ASYNC16(smb + SMEM_TILE(buf, mat) + off, sp);
        }
        CP_COMMIT();
    };

    issue_chunk(0, 0);

    // precompute ldmatrix lane addressing pieces
    const int la7 = lane & 7;
    const int arow_off = (lane >> 3) & 1;   // A: +8 rows for groups 1,3
    const int akseg   = (lane >> 4) & 1;    // A: +16B for groups 2,3
    const int brow_off = (lane >> 4) & 1;   // B: +8 rows for groups 2,3
    const int bkseg   = (lane >> 3) & 1;    // B: +16B for groups 1,3

    for (int kc = 0; kc < 8; kc++) {
        CP_WAIT0();
        __syncthreads();
        if (kc < 7) issue_chunk(kc + 1, (kc + 1) & 1);

        const int buf = kc & 1;
        const uint32_t aHi = smb + SMEM_TILE(buf, 0);
        const uint32_t aLo = smb + SMEM_TILE(buf, 1);
        const uint32_t bHi = smb + SMEM_TILE(buf, 2);
        const uint32_t bLo = smb + SMEM_TILE(buf, 3);

#pragma unroll
        for (int ks = 0; ks < 4; ks++) {
            uint32_t ahi[2][4], alo[2][4], bhi[2][4], blo[2][4];
#pragma unroll
            for (int mf = 0; mf < 2; mf++) {
                int row = wm + mf * 16 + la7 + arow_off * 8;
                uint32_t off = (uint32_t)(row * 128 + ks * 32 + akseg * 16);
                off ^= (uint32_t)((row & 7) * 16);
                LDMATRIX_X4(ahi[mf][0], ahi[mf][1], ahi[mf][2], ahi[mf][3], aHi + off);
                LDMATRIX_X4(alo[mf][0], alo[mf][1], alo[mf][2], alo[mf][3], aLo + off);
            }
#pragma unroll
            for (int p = 0; p < 2; p++) {
                int row = wn + p * 16 + la7 + brow_off * 8;
                uint32_t off = (uint32_t)(row * 128 + ks * 32 + bkseg * 16);
                off ^= (uint32_t)((row & 7) * 16);
                LDMATRIX_X4(bhi[p][0], bhi[p][1], bhi[p][2], bhi[p][3], bHi + off);
                LDMATRIX_X4(blo[p][0], blo[p][1], blo[p][2], blo[p][3], bLo + off);
            }
#pragma unroll
            for (int mf = 0; mf < 2; mf++)
#pragma unroll
                for (int nf = 0; nf < 4; nf++) {
                    const int p = nf >> 1, s = (nf & 1) * 2;
                    float* c = acc[mf][nf];
                    MMA_BF16(c[0], c[1], c[2], c[3],
                             ahi[mf][0], ahi[mf][1], ahi[mf][2], ahi[mf][3],
                             bhi[p][s], bhi[p][s + 1]);
                    MMA_BF16(c[0], c[1], c[2], c[3],
                             ahi[mf][0], ahi[mf][1], ahi[mf][2], ahi[mf][3],
                             blo[p][s], blo[p][s + 1]);
                    MMA_BF16(c[0], c[1], c[2], c[3],
                             alo[mf][0], alo[mf][1], alo[mf][2], alo[mf][3],
                             bhi[p][s], bhi[p][s + 1]);
                }
        }
    }

    // ---- stage z tiles to smem (reuse buffer 0 region: 16KB needed) ----
    float* zs = (float*)smp;
    {
        const int cr = lane >> 2, cc = (lane & 3) * 2;
#pragma unroll
        for (int mf = 0; mf < 2; mf++)
#pragma unroll
            for (int nf = 0; nf < 4; nf++) {
                int row = wm + mf * 16 + cr;
                int col = wn + nf * 8 + cc;
                *(float2*)&zs[row * 64 + col]       = make_float2(acc[mf][nf][0], acc[mf][nf][1]);
                *(float2*)&zs[(row + 8) * 64 + col] = make_float2(acc[mf][nf][2], acc[mf][nf][3]);
            }
    }
    __syncthreads();

    // ---- fused LSTM cell epilogue: 64 rows x 16 units = 1024 cells ----
    const float* cin = (t == 0) ? c0 : g_c;
    __nv_bfloat16* dsthi = g_hb_hi[t & 1];
    __nv_bfloat16* dstlo = g_hb_lo[t & 1];
#pragma unroll
    for (int it = 0; it < 8; it++) {
        int cell = it * 128 + tid;
        int r = cell >> 4, ul = cell & 15;
        int b = b0 + r;
        int u = u0g + ul;
        bool msk = __ldg(seq + (size_t)b * kT + t) != 0;
        float4 z4 = *(const float4*)&zs[r * 64 + ul * 4];
        const float* zp = g_zpre + ((size_t)b * kT + t) * kG;
        float zi = z4.x + __ldg(zp + u);
        float zf = z4.y + __ldg(zp + 512 + u);
        float zg = z4.z + __ldg(zp + 1024 + u);
        float zo = z4.w + __ldg(zp + 1536 + u);
        float ig = fast_sig(zi);
        float fg = fast_sig(zf);
        float og = fast_sig(zo);
        float cold = __ldg(cin + (size_t)b * kUnits + u);
        float cnew = fmaf(fg, cold, ig * fast_tanh(zg));
        float hnew = og * fast_tanh(cnew);
        if (!msk) {
            cnew = cold;
            hnew = __ldg(hprev_f32 + (size_t)b * hstride + u);
        }
        g_c[(size_t)b * kUnits + u] = cnew;
        out[(size_t)b * (kT * kUnits) + (size_t)t * kUnits + u] = hnew;
        __nv_bfloat16 hi = __float2bfloat16(hnew);
        dsthi[(size_t)b * kUnits + u] = hi;
        dstlo[(size_t)b * kUnits + u] = __float2bfloat16(hnew - __bfloat162float(hi));
    }
}

// ---------------- finalize ----------------
__global__ __launch_bounds__(256) void finalize_kernel(float* __restrict__ out)
{
    int i = blockIdx.x * blockDim.x + threadIdx.x;
    if (i < kB * kUnits) {
        int b = i / kUnits;
        int u = i - b * kUnits;
        float* hfin = out + (size_t)kB * kT * kUnits;
        float* cfin = hfin + (size_t)kB * kUnits;
        hfin[i] = out[(size_t)b * (kT * kUnits) + (size_t)(kT - 1) * kUnits + u];
        cfin[i] = g_c[i];
    }
}

// ---------------- host ----------------
extern "C" void kernel_launch(void* const* d_in, const int* in_sizes, int n_in,
                              void* d_out, int out_size)
{
    const int*   seq  = (const int*)d_in[0];
    const float* h0   = (const float*)d_in[1];
    const float* c0   = (const float*)d_in[2];
    const float* emb  = (const float*)d_in[3];
    const float* W    = (const float*)d_in[4];
    const float* Umat = (const float*)d_in[5];
    const float* bias = (const float*)d_in[6];
    float* out = (float*)d_out;

    cudaFuncSetAttribute(step_mma_kernel, cudaFuncAttributeMaxDynamicSharedMemorySize, DYN_SMEM);

    prep_kernel<<<kG + 8, 128>>>(Umat, h0);
    precompute_kernel<<<dim3(kG / 128, (kB * kT) / 128), 256>>>(seq, emb, W, bias);

    for (int t = 0; t < kT; t++) {
        const float* hprev = t ? (out + (size_t)(t - 1) * kUnits) : h0;
        int hstride = t ? (kT * kUnits) : kUnits;
        step_mma_kernel<<<dim3(32, 8), 128, DYN_SMEM>>>(t, seq, hprev, hstride, c0, out);
    }

    finalize_kernel<<<(kB * kUnits + 255) / 256, 256>>>(out);
}

// round 6
// speedup vs baseline: 4.7892x; 1.5412x over previous
#include <cuda_runtime.h>
#include <cuda_bf16.h>
#include <cstdint>
#include <math.h>

#define kVocab 50000
#define kEmbed 300
#define kEmbP  320      /* padded K for precompute */
#define kUnits 512
#define kT 128
#define kB 512
#define kG 2048  /* 4*UNITS */

// ---------------- global scratch ----------------
__device__ float g_zpre[(size_t)kB * kT * kG];                 // pre-activations [b*T+t][2048]
__device__ float g_c[(size_t)kB * kUnits];                     // c state [b][u]
__device__ __align__(128) __nv_bfloat16 g_u_hi[kG * kUnits];   // U^T gate-interleaved [n'][k]
__device__ __align__(128) __nv_bfloat16 g_u_lo[kG * kUnits];
__device__ __align__(128) __nv_bfloat16 g_hb_hi[2][kB * kUnits]; // h bf16 hi, double buffered [b][k]
__device__ __align__(128) __nv_bfloat16 g_hb_lo[2][kB * kUnits];
__device__ __align__(128) __nv_bfloat16 g_emb_hi[(size_t)kVocab * kEmbP]; // padded emb
__device__ __align__(128) __nv_bfloat16 g_emb_lo[(size_t)kVocab * kEmbP];
__device__ __align__(128) __nv_bfloat16 g_wt_hi[kG * kEmbP];   // W^T [n][kpad]
__device__ __align__(128) __nv_bfloat16 g_wt_lo[kG * kEmbP];

// ---------------- helpers ----------------
__device__ __forceinline__ uint32_t smem_u32(const void* p) {
    uint32_t a;
    asm("{ .reg .u64 t; cvta.to.shared.u64 t, %1; cvt.u32.u64 %0, t; }" : "=r"(a) : "l"(p));
    return a;
}
#define CP_ASYNC16(dst, src) \
    asm volatile("cp.async.ca.shared.global [%0], [%1], 16;" :: "r"(dst), "l"(src) : "memory")
#define CP_COMMIT() asm volatile("cp.async.commit_group;" ::: "memory")
#define CP_WAIT0()  asm volatile("cp.async.wait_group 0;" ::: "memory")
#define CP_WAIT1()  asm volatile("cp.async.wait_group 1;" ::: "memory")

#define LDMATRIX_X4(r0, r1, r2, r3, addr) \
    asm volatile("ldmatrix.sync.aligned.m8n8.x4.shared.b16 {%0,%1,%2,%3}, [%4];" \
        : "=r"(r0), "=r"(r1), "=r"(r2), "=r"(r3) : "r"(addr))

#define MMA_BF16(c0, c1, c2, c3, a0, a1, a2, a3, b0, b1) \
    asm volatile("mma.sync.aligned.m16n8k16.row.col.f32.bf16.bf16.f32 " \
        "{%0,%1,%2,%3}, {%4,%5,%6,%7}, {%8,%9}, {%0,%1,%2,%3};" \
        : "+f"(c0), "+f"(c1), "+f"(c2), "+f"(c3) \
        : "r"(a0), "r"(a1), "r"(a2), "r"(a3), "r"(b0), "r"(b1))

__device__ __forceinline__ float fast_ex2(float x) { float y; asm("ex2.approx.ftz.f32 %0, %1;" : "=f"(y) : "f"(x)); return y; }
__device__ __forceinline__ float fast_sig(float x) { return __fdividef(1.f, 1.f + fast_ex2(-1.4426950408889634f * x)); }
__device__ __forceinline__ float fast_tanh(float x) {
    float ax = fabsf(x);
    float e = fast_ex2(-2.8853900817779268f * ax);
    float t = __fdividef(1.f - e, 1.f + e);
    return copysignf(t, x);
}
__device__ __forceinline__ void split_bf16(float v, __nv_bfloat16& hi, __nv_bfloat16& lo) {
    hi = __float2bfloat16(v);
    lo = __float2bfloat16(v - __bfloat162float(hi));
}

// ---------------- prep: convert/split/transpose all operands ----------------
__global__ __launch_bounds__(128) void prep_kernel(const float* __restrict__ U,
                                                   const float* __restrict__ h0,
                                                   const float* __restrict__ W,
                                                   const float* __restrict__ emb) {
    int blk = blockIdx.x;
    if (blk < kG) {                       // U^T gate-interleaved row n' = u*4+g <- U[:, g*512+u]
        int np = blk;
        int n = (np & 3) * kUnits + (np >> 2);
        for (int k = threadIdx.x; k < kUnits; k += 128) {
            __nv_bfloat16 hi, lo;
            split_bf16(__ldg(U + (size_t)k * kG + n), hi, lo);
            g_u_hi[np * kUnits + k] = hi;
            g_u_lo[np * kUnits + k] = lo;
        }
    } else if (blk < kG + 8) {            // h0 -> bf16 hi/lo into buffer 1
        int r0 = (blk - kG) * 64;
        for (int i = threadIdx.x; i < 64 * kUnits; i += 128) {
            int r = r0 + (i >> 9), k = i & 511;
            __nv_bfloat16 hi, lo;
            split_bf16(__ldg(h0 + (size_t)r * kUnits + k), hi, lo);
            g_hb_hi[1][r * kUnits + k] = hi;
            g_hb_lo[1][r * kUnits + k] = lo;
        }
    } else if (blk < kG + 8 + kG) {       // W^T row n (natural order), padded K
        int n = blk - kG - 8;
        for (int k = threadIdx.x; k < kEmbP; k += 128) {
            float v = (k < kEmbed) ? __ldg(W + (size_t)k * kG + n) : 0.f;
            __nv_bfloat16 hi, lo;
            split_bf16(v, hi, lo);
            g_wt_hi[n * kEmbP + k] = hi;
            g_wt_lo[n * kEmbP + k] = lo;
        }
    } else {                              // emb rows, padded: 8 rows per block
        int r0 = (blk - kG - 8 - kG) * 8;
        for (int rr = 0; rr < 8; rr++) {
            int row = r0 + rr;
            if (row >= kVocab) break;
            for (int k = threadIdx.x; k < kEmbP; k += 128) {
                float v = (k < kEmbed) ? __ldg(emb + (size_t)row * kEmbed + k) : 0.f;
                __nv_bfloat16 hi, lo;
                split_bf16(v, hi, lo);
                g_emb_hi[(size_t)row * kEmbP + k] = hi;
                g_emb_lo[(size_t)row * kEmbP + k] = lo;
            }
        }
    }
}

// ---------------- precompute Zpre via mma.sync ----------------
// grid (16 n-tiles, 512 b), 256 thr. CTA tile M=128(t) x N=128(n), K=320 in 5 chunks of 64.
// 2 SMEM stages, 1-deep lookahead (no stage collision).
#define PC_STG 65536
#define PC_DYN 131072

extern "C" __global__ void __launch_bounds__(256, 1) precompute_mma_kernel(
    const int* __restrict__ seq, const float* __restrict__ bias)
{
    extern __shared__ __align__(1024) char smp[];
    const uint32_t smb = smem_u32(smp);
    __shared__ int toks[128];

    const int tid = threadIdx.x;
    const int wid = tid >> 5, lane = tid & 31;
    const int nt = blockIdx.x, b = blockIdx.y;
    const int n0 = nt * 128;

    if (tid < 128) toks[tid] = seq[(size_t)b * kT + tid];
    __syncthreads();

    const int wm = (wid & 1) * 64;
    const int wn = (wid >> 1) * 32;

    float acc[4][4][4];
#pragma unroll
    for (int i = 0; i < 4; i++)
#pragma unroll
        for (int j = 0; j < 4; j++)
#pragma unroll
            for (int q = 0; q < 4; q++) acc[i][j][q] = 0.f;

    auto issue_chunk = [&](int kc, int stg) {
#pragma unroll
        for (int i = 0; i < 16; i++) {
            int idx = i * 256 + tid;
            uint32_t dst;
            const __nv_bfloat16* src;
            if (idx < 2048) {         // A: emb gather
                int mat = idx >> 10, r = (idx >> 3) & 127, q = idx & 7;
                src = (mat ? g_emb_lo : g_emb_hi) + (size_t)toks[r] * kEmbP + kc * 64 + q * 8;
                uint32_t off = (uint32_t)(r * 128 + ((q ^ (r & 7)) * 16));
                dst = smb + stg * PC_STG + mat * 16384 + off;
            } else {                  // B: W^T rows
                int idxB = idx - 2048;
                int mat = idxB >> 10, r = (idxB >> 3) & 127, q = idxB & 7;
                src = (mat ? g_wt_lo : g_wt_hi) + (size_t)(n0 + r) * kEmbP + kc * 64 + q * 8;
                uint32_t off = (uint32_t)(r * 128 + ((q ^ (r & 7)) * 16));
                dst = smb + stg * PC_STG + 32768 + mat * 16384 + off;
            }
            CP_ASYNC16(dst, src);
        }
        CP_COMMIT();
    };

    issue_chunk(0, 0);

    const int la7 = lane & 7;
    const int arow_off = (lane >> 3) & 1;
    const int akseg   = (lane >> 4) & 1;
    const int brow_off = (lane >> 4) & 1;
    const int bkseg   = (lane >> 3) & 1;

    for (int kc = 0; kc < 5; kc++) {
        CP_WAIT0();
        __syncthreads();
        if (kc < 4) issue_chunk(kc + 1, (kc + 1) & 1);

        const uint32_t base = smb + (kc & 1) * PC_STG;
#pragma unroll
        for (int ks = 0; ks < 4; ks++) {
            uint32_t ahi[4][4], alo[4][4], bhi[2][4], blo[2][4];
#pragma unroll
            for (int mf = 0; mf < 4; mf++) {
                int row = wm + mf * 16 + la7 + arow_off * 8;
                uint32_t off = (uint32_t)(row * 128 + ks * 32 + akseg * 16);
                off ^= (uint32_t)((row & 7) * 16);
                LDMATRIX_X4(ahi[mf][0], ahi[mf][1], ahi[mf][2], ahi[mf][3], base + off);
                LDMATRIX_X4(alo[mf][0], alo[mf][1], alo[mf][2], alo[mf][3], base + 16384 + off);
            }
#pragma unroll
            for (int p = 0; p < 2; p++) {
                int row = wn + p * 16 + la7 + brow_off * 8;
                uint32_t off = (uint32_t)(row * 128 + ks * 32 + bkseg * 16);
                off ^= (uint32_t)((row & 7) * 16);
                LDMATRIX_X4(bhi[p][0], bhi[p][1], bhi[p][2], bhi[p][3], base + 32768 + off);
                LDMATRIX_X4(blo[p][0], blo[p][1], blo[p][2], blo[p][3], base + 49152 + off);
            }
#pragma unroll
            for (int mf = 0; mf < 4; mf++)
#pragma unroll
                for (int nf = 0; nf < 4; nf++) {
                    const int p = nf >> 1, s = (nf & 1) * 2;
                    float* c = acc[mf][nf];
                    MMA_BF16(c[0], c[1], c[2], c[3],
                             ahi[mf][0], ahi[mf][1], ahi[mf][2], ahi[mf][3],
                             bhi[p][s], bhi[p][s + 1]);
                    MMA_BF16(c[0], c[1], c[2], c[3],
                             ahi[mf][0], ahi[mf][1], ahi[mf][2], ahi[mf][3],
                             blo[p][s], blo[p][s + 1]);
                    MMA_BF16(c[0], c[1], c[2], c[3],
                             alo[mf][0], alo[mf][1], alo[mf][2], alo[mf][3],
                             bhi[p][s], bhi[p][s + 1]);
                }
        }
    }

    // stage 128x128 f32 tile, then coalesced write with bias add
    __syncthreads();
    float* zs = (float*)smp;
    {
        const int cr = lane >> 2, cc = (lane & 3) * 2;
#pragma unroll
        for (int mf = 0; mf < 4; mf++)
#pragma unroll
            for (int nf = 0; nf < 4; nf++) {
                int row = wm + mf * 16 + cr;
                int col = wn + nf * 8 + cc;
                *(float2*)&zs[row * 128 + col]       = make_float2(acc[mf][nf][0], acc[mf][nf][1]);
                *(float2*)&zs[(row + 8) * 128 + col] = make_float2(acc[mf][nf][2], acc[mf][nf][3]);
            }
    }
    __syncthreads();

    // FIX (R5 bug): 16 iterations to cover ALL 128 rows (was 8 -> half the tile
    // unwritten -> rel_err 0.70).
    const int cseg = tid & 31;
    float4 bv = __ldg((const float4*)(bias + n0 + cseg * 4));
#pragma unroll
    for (int i = 0; i < 16; i++) {
        int r = i * 8 + (tid >> 5);
        float4 v = *(const float4*)&zs[r * 128 + cseg * 4];
        v.x += bv.x; v.y += bv.y; v.z += bv.z; v.w += bv.w;
        *(float4*)(g_zpre + ((size_t)b * kT + r) * kG + n0 + cseg * 4) = v;
    }
}

// ---------------- mma.sync LSTM step ----------------
// grid (16 n-tiles, 8 m-tiles) = 128 CTAs, 256 thr (8 warps, 2x4), warp tile 32x32.
// CTA tile: M=64 batch x N=128 n' (32 units x 4 gates), K=512 in 8 chunks of 64.
// smem: 3 stages x (A hi/lo 16KB + B hi/lo 32KB) = 144KB.
#define ST_STG 49152
#define ST_DYN 147456

extern "C" __global__ void __launch_bounds__(256, 1) step_mma_kernel(
    int t,
    const int* __restrict__ seq,
    const float* __restrict__ hprev_f32, int hstride,
    const float* __restrict__ c0,
    float* __restrict__ out)
{
    extern __shared__ __align__(1024) char smp[];
    const uint32_t smb = smem_u32(smp);

    const int tid = threadIdx.x;
    const int wid = tid >> 5, lane = tid & 31;
    const int nt = blockIdx.x, mt = blockIdx.y;
    const int b0 = mt * 64;
    const int n0 = nt * 128;
    const int u0g = nt * 32;

    // ---- epilogue operand prefetch (overlaps GEMM) ----
    const int ul = tid & 31;
    float zpf[8][4], cpre[8];
    int seqv[8];
    {
        const float* cin = (t == 0) ? c0 : g_c;
#pragma unroll
        for (int it = 0; it < 8; it++) {
            int r = it * 8 + (tid >> 5);
            int bb = b0 + r;
            const float* zp = g_zpre + ((size_t)bb * kT + t) * kG;
#pragma unroll
            for (int g = 0; g < 4; g++)
                zpf[it][g] = __ldg(zp + g * kUnits + u0g + ul);
            cpre[it] = __ldg(cin + (size_t)bb * kUnits + u0g + ul);
            seqv[it] = __ldg(seq + (size_t)bb * kT + t);
        }
    }

    const __nv_bfloat16* srcA_hi = g_hb_hi[(t + 1) & 1] + (size_t)b0 * kUnits;
    const __nv_bfloat16* srcA_lo = g_hb_lo[(t + 1) & 1] + (size_t)b0 * kUnits;
    const __nv_bfloat16* srcB_hi = g_u_hi + (size_t)n0 * kUnits;
    const __nv_bfloat16* srcB_lo = g_u_lo + (size_t)n0 * kUnits;

    const int wm = (wid & 1) * 32;
    const int wn = (wid >> 1) * 32;

    float acc[2][4][4];
#pragma unroll
    for (int i = 0; i < 2; i++)
#pragma unroll
        for (int j = 0; j < 4; j++)
#pragma unroll
            for (int q = 0; q < 4; q++) acc[i][j][q] = 0.f;

    auto issue_chunk = [&](int kc, int stg) {
#pragma unroll
        for (int i = 0; i < 12; i++) {
            int idx = i * 256 + tid;
            uint32_t dst;
            const __nv_bfloat16* src;
            if (idx < 1024) {         // A: h rows (64)
                int mat = idx >> 9, r = (idx >> 3) & 63, q = idx & 7;
                src = (mat ? srcA_lo : srcA_hi) + (size_t)r * kUnits + kc * 64 + q * 8;
                uint32_t off = (uint32_t)(r * 128 + ((q ^ (r & 7)) * 16));
                dst = smb + stg * ST_STG + mat * 8192 + off;
            } else {                  // B: U rows (128)
                int idxB = idx - 1024;
                int mat = idxB >> 10, r = (idxB >> 3) & 127, q = idxB & 7;
                src = (mat ? srcB_lo : srcB_hi) + (size_t)r * kUnits + kc * 64 + q * 8;
                uint32_t off = (uint32_t)(r * 128 + ((q ^ (r & 7)) * 16));
                dst = smb + stg * ST_STG + 16384 + mat * 16384 + off;
            }
            CP_ASYNC16(dst, src);
        }
        CP_COMMIT();
    };

    issue_chunk(0, 0);
    issue_chunk(1, 1);

    const int la7 = lane & 7;
    const int arow_off = (lane >> 3) & 1;
    const int akseg   = (lane >> 4) & 1;
    const int brow_off = (lane >> 4) & 1;
    const int bkseg   = (lane >> 3) & 1;

    for (int kc = 0; kc < 8; kc++) {
        if (kc < 6) { CP_WAIT1(); } else { CP_WAIT0(); }
        __syncthreads();
        if (kc < 6) issue_chunk(kc + 2, (kc + 2) % 3);

        const uint32_t base = smb + (kc % 3) * ST_STG;
#pragma unroll
        for (int ks = 0; ks < 4; ks++) {
            uint32_t ahi[2][4], alo[2][4], bhi[2][4], blo[2][4];
#pragma unroll
            for (int mf = 0; mf < 2; mf++) {
                int row = wm + mf * 16 + la7 + arow_off * 8;
                uint32_t off = (uint32_t)(row * 128 + ks * 32 + akseg * 16);
                off ^= (uint32_t)((row & 7) * 16);
                LDMATRIX_X4(ahi[mf][0], ahi[mf][1], ahi[mf][2], ahi[mf][3], base + off);
                LDMATRIX_X4(alo[mf][0], alo[mf][1], alo[mf][2], alo[mf][3], base + 8192 + off);
            }
#pragma unroll
            for (int p = 0; p < 2; p++) {
                int row = wn + p * 16 + la7 + brow_off * 8;
                uint32_t off = (uint32_t)(row * 128 + ks * 32 + bkseg * 16);
                off ^= (uint32_t)((row & 7) * 16);
                LDMATRIX_X4(bhi[p][0], bhi[p][1], bhi[p][2], bhi[p][3], base + 16384 + off);
                LDMATRIX_X4(blo[p][0], blo[p][1], blo[p][2], blo[p][3], base + 32768 + off);
            }
#pragma unroll
            for (int mf = 0; mf < 2; mf++)
#pragma unroll
                for (int nf = 0; nf < 4; nf++) {
                    const int p = nf >> 1, s = (nf & 1) * 2;
                    float* c = acc[mf][nf];
                    MMA_BF16(c[0], c[1], c[2], c[3],
                             ahi[mf][0], ahi[mf][1], ahi[mf][2], ahi[mf][3],
                             bhi[p][s], bhi[p][s + 1]);
                    MMA_BF16(c[0], c[1], c[2], c[3],
                             ahi[mf][0], ahi[mf][1], ahi[mf][2], ahi[mf][3],
                             blo[p][s], blo[p][s + 1]);
                    MMA_BF16(c[0], c[1], c[2], c[3],
                             alo[mf][0], alo[mf][1], alo[mf][2], alo[mf][3],
                             bhi[p][s], bhi[p][s + 1]);
                }
        }
    }

    // ---- stage z (h@U part) to smem: 64x128 f32 = 32KB (reuse stage 0) ----
    __syncthreads();
    float* zs = (float*)smp;
    {
        const int cr = lane >> 2, cc = (lane & 3) * 2;
#pragma unroll
        for (int mf = 0; mf < 2; mf++)
#pragma unroll
            for (int nf = 0; nf < 4; nf++) {
                int row = wm + mf * 16 + cr;
                int col = wn + nf * 8 + cc;
                *(float2*)&zs[row * 128 + col]       = make_float2(acc[mf][nf][0], acc[mf][nf][1]);
                *(float2*)&zs[(row + 8) * 128 + col] = make_float2(acc[mf][nf][2], acc[mf][nf][3]);
            }
    }
    __syncthreads();

    // ---- fused LSTM epilogue ----
    __nv_bfloat16* dsthi = g_hb_hi[t & 1];
    __nv_bfloat16* dstlo = g_hb_lo[t & 1];
#pragma unroll
    for (int it = 0; it < 8; it++) {
        int r = it * 8 + (tid >> 5);
        int b = b0 + r;
        int u = u0g + ul;
        float4 z4 = *(const float4*)&zs[r * 128 + ul * 4];
        float zi = z4.x + zpf[it][0];
        float zf = z4.y + zpf[it][1];
        float zg = z4.z + zpf[it][2];
        float zo = z4.w + zpf[it][3];
        float ig = fast_sig(zi);
        float fg = fast_sig(zf);
        float og = fast_sig(zo);
        float cold = cpre[it];
        float cnew = fmaf(fg, cold, ig * fast_tanh(zg));
        float hnew = og * fast_tanh(cnew);
        if (seqv[it] == 0) {
            cnew = cold;
            hnew = __ldg(hprev_f32 + (size_t)b * hstride + u);
        }
        g_c[(size_t)b * kUnits + u] = cnew;
        out[(size_t)b * (kT * kUnits) + (size_t)t * kUnits + u] = hnew;
        __nv_bfloat16 hi, lo;
        split_bf16(hnew, hi, lo);
        dsthi[(size_t)b * kUnits + u] = hi;
        dstlo[(size_t)b * kUnits + u] = lo;
    }
}

// ---------------- finalize ----------------
__global__ __launch_bounds__(256) void finalize_kernel(float* __restrict__ out)
{
    int i = blockIdx.x * blockDim.x + threadIdx.x;
    if (i < kB * kUnits) {
        int b = i / kUnits;
        int u = i - b * kUnits;
        float* hfin = out + (size_t)kB * kT * kUnits;
        float* cfin = hfin + (size_t)kB * kUnits;
        hfin[i] = out[(size_t)b * (kT * kUnits) + (size_t)(kT - 1) * kUnits + u];
        cfin[i] = g_c[i];
    }
}

// ---------------- host ----------------
extern "C" void kernel_launch(void* const* d_in, const int* in_sizes, int n_in,
                              void* d_out, int out_size)
{
    const int*   seq  = (const int*)d_in[0];
    const float* h0   = (const float*)d_in[1];
    const float* c0   = (const float*)d_in[2];
    const float* emb  = (const float*)d_in[3];
    const float* W    = (const float*)d_in[4];
    const float* Umat = (const float*)d_in[5];
    const float* bias = (const float*)d_in[6];
    float* out = (float*)d_out;

    static int configured = 0;
    if (!configured) {
        cudaFuncSetAttribute(precompute_mma_kernel, cudaFuncAttributeMaxDynamicSharedMemorySize, PC_DYN);
        cudaFuncSetAttribute(step_mma_kernel, cudaFuncAttributeMaxDynamicSharedMemorySize, ST_DYN);
        configured = 1;
    }

    const int embBlocks = (kVocab + 7) / 8;
    prep_kernel<<<kG + 8 + kG + embBlocks, 128>>>(Umat, h0, W, emb);

    precompute_mma_kernel<<<dim3(16, kB), 256, PC_DYN>>>(seq, bias);

    for (int t = 0; t < kT; t++) {
        const float* hprev = t ? (out + (size_t)(t - 1) * kUnits) : h0;
        int hstride = t ? (kT * kUnits) : kUnits;
        step_mma_kernel<<<dim3(16, 8), 256, ST_DYN>>>(t, seq, hprev, hstride, c0, out);
    }

    finalize_kernel<<<(kB * kUnits + 255) / 256, 256>>>(out);
}